// round 2
// baseline (speedup 1.0000x reference)
#include <cuda_runtime.h>

// ---------------------------------------------------------------------------
// LinkWeightDecoder: out[e] = MLP(concat(emb[src_e], emb[dst_e]))
// Strategy:
//   K1: P[n][0:128]  = emb[n] @ W1[:128]  + b1   (src projection, bias folded)
//       P[n][128:256]= emb[n] @ W1[128:]         (dst projection)
//   K2: h1 = relu(P[src][0:128] + P[dst][128:256])   (gather+add, no GEMM)
//       h2 = relu(h1 @ W2 + b2) ; out = h2 @ W3 + b3
// All fp32; inner products use packed fma.rn.f32x2 (2x fp32 rate on sm_100).
// edge_index dtype (int32 vs int64) detected at runtime by a tiny kernel.
// ---------------------------------------------------------------------------

#define MAXN 100000

__device__ float g_P[MAXN * 256];   // per-node projections scratch (102.4 MB)
__device__ int   g_idx64;           // 1 if edge_index is int64, 0 if int32

__device__ __forceinline__ unsigned long long pack2(float lo, float hi) {
    unsigned long long r;
    asm("mov.b64 %0, {%1, %2};" : "=l"(r) : "f"(lo), "f"(hi));
    return r;
}
__device__ __forceinline__ void unpack2(unsigned long long v, float& lo, float& hi) {
    asm("mov.b64 {%0, %1}, %2;" : "=f"(lo), "=f"(hi) : "l"(v));
}
__device__ __forceinline__ void fma2(unsigned long long& d,
                                     unsigned long long a, unsigned long long b) {
    asm("fma.rn.f32x2 %0, %1, %2, %0;" : "+l"(d) : "l"(a), "l"(b));
}

// ---------------------------------------------------------------------------
// Detect index dtype: for int64 (little-endian, values in [0, N), N < 2^31)
// every odd 32-bit word of the buffer is 0. For int32, odd words are random
// node ids (zero w.p. 1e-5 each). Check 64 of them.
// ---------------------------------------------------------------------------
__global__ void detect_idx_kernel(const int* __restrict__ eidx_w, int n_words) {
    int allzero = 1;
#pragma unroll 1
    for (int i = 0; i < 64; i++) {
        int p = 2 * i + 1;
        if (p < n_words && eidx_w[p] != 0) allzero = 0;
    }
    g_idx64 = allzero;
}

// ---------------------------------------------------------------------------
// Kernel 1: P = emb @ [W1a | W1b]   ([N,128] x [128,256])
// Block: 256 threads, tile 64 nodes x 256 outs. Warp grid 4(out)x2(node),
// lane grid 8(out)x4(node). Thread microtile: 8 nodes x 8 outs (4 f32x2).
// K staged in chunks of 32 (smem: W1 chunk 33.3KB + emb chunk 8.4KB).
// ---------------------------------------------------------------------------
__global__ __launch_bounds__(256, 2)
void precompute_kernel(const float* __restrict__ emb,
                       const float* __restrict__ W1,
                       const float* __restrict__ b1, int N) {
    __shared__ float sW1c[32 * 260];   // [dk][o] padded 256->260
    __shared__ float sEmb[64 * 33];    // [node][dk] padded 32->33

    const int tid  = threadIdx.x;
    const int lane = tid & 31, w = tid >> 5;
    const int wx = w & 3, wy = w >> 2;
    const int lx = lane & 7, ly = lane >> 3;
    const int o0  = wx * 64 + lx * 8;      // output base (0..248)
    const int nl0 = wy * 32 + ly * 8;      // local node base (0..56)
    const int gn0 = blockIdx.x * 64;

    unsigned long long acc[8][4];
#pragma unroll
    for (int i = 0; i < 8; i++)
#pragma unroll
        for (int p = 0; p < 4; p++) acc[i][p] = 0ull;

    for (int kc = 0; kc < 4; kc++) {
        // stage emb chunk [64 nodes][32 k]
#pragma unroll
        for (int it = 0; it < 2; it++) {
            int slot = it * 256 + tid;
            int node = slot >> 3, kg = slot & 7;
            int gnode = gn0 + node; if (gnode >= N) gnode = N - 1;
            float4 v = *(const float4*)&emb[(long long)gnode * 128 + kc * 32 + kg * 4];
            float* dp = &sEmb[node * 33 + kg * 4];
            dp[0] = v.x; dp[1] = v.y; dp[2] = v.z; dp[3] = v.w;
        }
        // stage W1 chunk: Bmat[dk][o] = o<128 ? W1[k][o] : W1[k+128][o-128]
#pragma unroll
        for (int it = 0; it < 8; it++) {
            int slot = it * 256 + tid;
            int dk = slot >> 6, og = slot & 63;
            int o = og * 4;
            int gk = kc * 32 + dk;
            const float* sp = (o < 128) ? &W1[gk * 128 + o]
                                        : &W1[(gk + 128) * 128 + (o - 128)];
            *(float4*)&sW1c[dk * 260 + o] = *(const float4*)sp;
        }
        __syncthreads();

#pragma unroll
        for (int dk = 0; dk < 32; dk++) {
            const ulonglong2* wp = (const ulonglong2*)&sW1c[dk * 260 + o0];
            ulonglong2 wa = wp[0], wb = wp[1];
#pragma unroll
            for (int i = 0; i < 8; i++) {
                float ev = sEmb[(nl0 + i) * 33 + dk];
                unsigned long long ee = pack2(ev, ev);
                fma2(acc[i][0], ee, wa.x);
                fma2(acc[i][1], ee, wa.y);
                fma2(acc[i][2], ee, wb.x);
                fma2(acc[i][3], ee, wb.y);
            }
        }
        __syncthreads();
    }

    // epilogue: fold b1 into the src half, store
    float bb[8];
#pragma unroll
    for (int j = 0; j < 8; j++) bb[j] = (o0 < 128) ? __ldg(&b1[o0 + j]) : 0.f;

#pragma unroll
    for (int i = 0; i < 8; i++) {
        int gnode = gn0 + nl0 + i;
        if (gnode < N) {
            float v[8];
#pragma unroll
            for (int p = 0; p < 4; p++) unpack2(acc[i][p], v[2 * p], v[2 * p + 1]);
#pragma unroll
            for (int j = 0; j < 8; j++) v[j] += bb[j];
            float4* op = (float4*)&g_P[(long long)gnode * 256 + o0];
            op[0] = make_float4(v[0], v[1], v[2], v[3]);
            op[1] = make_float4(v[4], v[5], v[6], v[7]);
        }
    }
}

// ---------------------------------------------------------------------------
// Kernel 2: per 64-edge tile: gather h1 = relu(P[src][:128]+P[dst][128:]),
// then h2 = relu(h1 @ W2 + b2), out = h2 @ W3 + b3.
// Block 256 threads. GEMM warp tile: 64 outs x 8 edges; lanes 16(out)x2(edge);
// thread microtile 4 edges x 4 outs (2 f32x2 per edge).
// ---------------------------------------------------------------------------
__global__ __launch_bounds__(256, 2)
void edge_kernel(const int* __restrict__ eidx_w,
                 const float* __restrict__ W2,
                 const float* __restrict__ b2,
                 const float* __restrict__ W3,
                 const float* __restrict__ b3,
                 float* __restrict__ out, int E, int N) {
    __shared__ float sH1[64 * 132];    // [edge][k] padded 128->132
    __shared__ float sW2[32 * 68];     // [dk][o]  padded 64->68
    __shared__ int   sSrc[64], sDst[64];
    __shared__ float sW3[64];

    const int tid = threadIdx.x;
    const int e0g = blockIdx.x * 64;
    const int stride = g_idx64 ? 2 : 1;   // words per index element

    // load indices (clamped so a bad index can never fault) + W3
    if (tid < 64) {
        int e = e0g + tid; if (e >= E) e = E - 1;
        int v = eidx_w[(long long)e * stride];
        sSrc[tid] = min(max(v, 0), N - 1);
    } else if (tid < 128) {
        int e = e0g + (tid - 64); if (e >= E) e = E - 1;
        int v = eidx_w[(long long)(E + e) * stride];
        sDst[tid - 64] = min(max(v, 0), N - 1);
    } else if (tid < 192) {
        sW3[tid - 128] = W3[tid - 128];
    }
    __syncthreads();

    // gather + add + relu -> sH1  (64 edges x 128 floats, mostly L2-resident)
    const float4* P4 = (const float4*)g_P;
#pragma unroll
    for (int it = 0; it < 8; it++) {
        int slot = it * 256 + tid;
        int e = slot >> 5, c = slot & 31;
        float4 a = __ldg(&P4[(long long)sSrc[e] * 64 + c]);        // src half (+b1)
        float4 b = __ldg(&P4[(long long)sDst[e] * 64 + 32 + c]);   // dst half
        float4 h;
        h.x = fmaxf(a.x + b.x, 0.f);
        h.y = fmaxf(a.y + b.y, 0.f);
        h.z = fmaxf(a.z + b.z, 0.f);
        h.w = fmaxf(a.w + b.w, 0.f);
        *(float4*)&sH1[e * 132 + c * 4] = h;
    }

    // layer 2 GEMM: [64 edges x 128] @ [128 x 64]
    const int lane = tid & 31, w = tid >> 5;
    const int lx = lane & 15, ly = lane >> 4;
    const int o0  = lx * 4;            // 0..60
    const int el0 = w * 8 + ly * 4;    // local edge base, 0..60

    unsigned long long acc[4][2];
#pragma unroll
    for (int i = 0; i < 4; i++) { acc[i][0] = 0ull; acc[i][1] = 0ull; }

    for (int kc = 0; kc < 4; kc++) {
        // stage W2 chunk [32 k][64 o]
#pragma unroll
        for (int it = 0; it < 2; it++) {
            int slot = it * 256 + tid;
            int dk = slot >> 4, og = slot & 15;
            *(float4*)&sW2[dk * 68 + og * 4] =
                *(const float4*)&W2[(kc * 32 + dk) * 64 + og * 4];
        }
        __syncthreads();   // also covers sH1 writes on kc==0

#pragma unroll
        for (int dk = 0; dk < 32; dk += 4) {
            int k = kc * 32 + dk;
            float4 hv[4];
#pragma unroll
            for (int i = 0; i < 4; i++)
                hv[i] = *(const float4*)&sH1[(el0 + i) * 132 + k];
#pragma unroll
            for (int kk = 0; kk < 4; kk++) {
                ulonglong2 wv = *(const ulonglong2*)&sW2[(dk + kk) * 68 + o0];
#pragma unroll
                for (int i = 0; i < 4; i++) {
                    float hx = (kk == 0) ? hv[i].x : (kk == 1) ? hv[i].y
                             : (kk == 2) ? hv[i].z : hv[i].w;
                    unsigned long long hh = pack2(hx, hx);
                    fma2(acc[i][0], hh, wv.x);
                    fma2(acc[i][1], hh, wv.y);
                }
            }
        }
        __syncthreads();
    }

    // epilogue: +b2, relu, dot with W3, warp-segment reduce, +b3
    float4 b2v = __ldg((const float4*)&b2[o0]);
    float w30 = sW3[o0], w31 = sW3[o0 + 1], w32 = sW3[o0 + 2], w33 = sW3[o0 + 3];
    float bias3 = __ldg(&b3[0]);

#pragma unroll
    for (int i = 0; i < 4; i++) {
        float v0, v1, v2, v3;
        unpack2(acc[i][0], v0, v1);
        unpack2(acc[i][1], v2, v3);
        float s = fmaxf(v0 + b2v.x, 0.f) * w30
                + fmaxf(v1 + b2v.y, 0.f) * w31
                + fmaxf(v2 + b2v.z, 0.f) * w32
                + fmaxf(v3 + b2v.w, 0.f) * w33;
        // reduce across the 16 lanes sharing this edge (xor stays in 16-group)
        s += __shfl_xor_sync(0xffffffffu, s, 8);
        s += __shfl_xor_sync(0xffffffffu, s, 4);
        s += __shfl_xor_sync(0xffffffffu, s, 2);
        s += __shfl_xor_sync(0xffffffffu, s, 1);
        if (lx == 0) {
            int e = e0g + el0 + i;
            if (e < E) out[e] = s + bias3;
        }
    }
}

// ---------------------------------------------------------------------------
extern "C" void kernel_launch(void* const* d_in, const int* in_sizes, int n_in,
                              void* d_out, int out_size) {
    const float* emb    = (const float*)d_in[0];
    const int*   eidx_w = (const int*)d_in[1];     // raw 32-bit words
    const float* W1     = (const float*)d_in[2];
    const float* b1     = (const float*)d_in[3];
    const float* W2     = (const float*)d_in[4];
    const float* b2     = (const float*)d_in[5];
    const float* W3     = (const float*)d_in[6];
    const float* b3     = (const float*)d_in[7];

    int N = in_sizes[0] / 128;   // node count
    int E = in_sizes[1] / 2;     // edge count (elements, dtype-independent)

    detect_idx_kernel<<<1, 1>>>(eidx_w, 2 * E);   // conservative word count
    precompute_kernel<<<(N + 63) / 64, 256>>>(emb, W1, b1, N);
    edge_kernel<<<(E + 63) / 64, 256>>>(eidx_w, W2, b2, W3, b3, (float*)d_out, E, N);
}

// round 4
// speedup vs baseline: 1.2260x; 1.2260x over previous
#include <cuda_runtime.h>

// ---------------------------------------------------------------------------
// LinkWeightDecoder: out[e] = MLP(concat(emb[src_e], emb[dst_e]))
//   K1: P[n][0:128]  = emb[n] @ W1[:128]  + b1   (src projection, bias folded)
//       P[n][128:256]= emb[n] @ W1[128:]         (dst projection)
//   K2 (persistent): per 64-edge tile:
//       h1 = relu(P[src][0:128] + P[dst][128:256])   (register-pipelined gather)
//       h2 = relu(h1 @ W2 + b2) ; out = h2 @ W3 + b3
// All fp32; inner products use packed fma.rn.f32x2 (2x fp32 rate on sm_100).
// edge_index dtype (int32 vs int64) detected per-block from the raw words.
// ---------------------------------------------------------------------------

#define MAXN 100000
#define NSM  148

// edge_kernel dynamic smem layout (floats):
//   sH1 : 64*128   (32 KB)
//   sW2 : 128*64   (32 KB)
//   sW3 : 64       (256 B)
#define SH1_FLOATS (64 * 128)
#define SW2_FLOATS (128 * 64)
#define EDGE_SMEM_BYTES ((SH1_FLOATS + SW2_FLOATS + 64) * 4)

__device__ float g_P[MAXN * 256];   // per-node projections scratch (102.4 MB)

__device__ __forceinline__ unsigned long long pack2(float lo, float hi) {
    unsigned long long r;
    asm("mov.b64 %0, {%1, %2};" : "=l"(r) : "f"(lo), "f"(hi));
    return r;
}
__device__ __forceinline__ void unpack2(unsigned long long v, float& lo, float& hi) {
    asm("mov.b64 {%0, %1}, %2;" : "=f"(lo), "=f"(hi) : "l"(v));
}
__device__ __forceinline__ void fma2(unsigned long long& d,
                                     unsigned long long a, unsigned long long b) {
    asm("fma.rn.f32x2 %0, %1, %2, %0;" : "+l"(d) : "l"(a), "l"(b));
}

// ---------------------------------------------------------------------------
// Kernel 1: P = emb @ [W1a | W1b]   ([N,128] x [128,256])
// ---------------------------------------------------------------------------
__global__ __launch_bounds__(256, 2)
void precompute_kernel(const float* __restrict__ emb,
                       const float* __restrict__ W1,
                       const float* __restrict__ b1, int N) {
    __shared__ float sW1c[32 * 260];   // [dk][o] padded 256->260
    __shared__ float sEmb[64 * 33];    // [node][dk] padded 32->33

    const int tid  = threadIdx.x;
    const int lane = tid & 31, w = tid >> 5;
    const int wx = w & 3, wy = w >> 2;
    const int lx = lane & 7, ly = lane >> 3;
    const int o0  = wx * 64 + lx * 8;      // output base (0..248)
    const int nl0 = wy * 32 + ly * 8;      // local node base (0..56)
    const int gn0 = blockIdx.x * 64;

    unsigned long long acc[8][4];
#pragma unroll
    for (int i = 0; i < 8; i++)
#pragma unroll
        for (int p = 0; p < 4; p++) acc[i][p] = 0ull;

    for (int kc = 0; kc < 4; kc++) {
#pragma unroll
        for (int it = 0; it < 2; it++) {
            int slot = it * 256 + tid;
            int node = slot >> 3, kg = slot & 7;
            int gnode = gn0 + node; if (gnode >= N) gnode = N - 1;
            float4 v = *(const float4*)&emb[(long long)gnode * 128 + kc * 32 + kg * 4];
            float* dp = &sEmb[node * 33 + kg * 4];
            dp[0] = v.x; dp[1] = v.y; dp[2] = v.z; dp[3] = v.w;
        }
#pragma unroll
        for (int it = 0; it < 8; it++) {
            int slot = it * 256 + tid;
            int dk = slot >> 6, og = slot & 63;
            int o = og * 4;
            int gk = kc * 32 + dk;
            const float* sp = (o < 128) ? &W1[gk * 128 + o]
                                        : &W1[(gk + 128) * 128 + (o - 128)];
            *(float4*)&sW1c[dk * 260 + o] = *(const float4*)sp;
        }
        __syncthreads();

#pragma unroll
        for (int dk = 0; dk < 32; dk++) {
            const ulonglong2* wp = (const ulonglong2*)&sW1c[dk * 260 + o0];
            ulonglong2 wa = wp[0], wb = wp[1];
#pragma unroll
            for (int i = 0; i < 8; i++) {
                float ev = sEmb[(nl0 + i) * 33 + dk];
                unsigned long long ee = pack2(ev, ev);
                fma2(acc[i][0], ee, wa.x);
                fma2(acc[i][1], ee, wa.y);
                fma2(acc[i][2], ee, wb.x);
                fma2(acc[i][3], ee, wb.y);
            }
        }
        __syncthreads();
    }

    float bb[8];
#pragma unroll
    for (int j = 0; j < 8; j++) bb[j] = (o0 < 128) ? __ldg(&b1[o0 + j]) : 0.f;

#pragma unroll
    for (int i = 0; i < 8; i++) {
        int gnode = gn0 + nl0 + i;
        if (gnode < N) {
            float v[8];
#pragma unroll
            for (int p = 0; p < 4; p++) unpack2(acc[i][p], v[2 * p], v[2 * p + 1]);
#pragma unroll
            for (int j = 0; j < 8; j++) v[j] += bb[j];
            float4* op = (float4*)&g_P[(long long)gnode * 256 + o0];
            op[0] = make_float4(v[0], v[1], v[2], v[3]);
            op[1] = make_float4(v[4], v[5], v[6], v[7]);
        }
    }
}

// ---------------------------------------------------------------------------
// Kernel 2 (persistent): W2 staged once; per-tile register-pipelined gather.
// Warp w handles edges {w, 8+w, ..., 56+w} of a tile for gather (lane = f4 col).
// GEMM: lanes 16(out)x2(edge), thread microtile 4 edges x 4 outs (f32x2 pairs).
// Dynamic smem (64.3 KB): sH1[64][128], sW2[128][64], sW3[64].
// ---------------------------------------------------------------------------
__global__ __launch_bounds__(256, 2)
void edge_kernel(const int* __restrict__ eidx_w,
                 const float* __restrict__ W2,
                 const float* __restrict__ b2,
                 const float* __restrict__ W3,
                 const float* __restrict__ b3,
                 float* __restrict__ out, int E, int N, int nTiles) {
    extern __shared__ float dsm[];
    float* sH1 = dsm;                      // [edge][k], stride 128
    float* sW2 = dsm + SH1_FLOATS;         // [k][o],    stride 64
    float* sW3 = sW2 + SW2_FLOATS;         // [64]
    __shared__ int sAny;

    const int tid  = threadIdx.x;
    const int lane = tid & 31, w = tid >> 5;

    // ---- one-time staging: W2, W3, index-dtype detection ----
    if (tid == 0) sAny = 0;
    __syncthreads();
    if (tid < 64) {
        // int64 (LE, values < 2^31) => all odd 32-bit words are 0
        if (eidx_w[2 * tid + 1] != 0) atomicOr(&sAny, 1);
    }
#pragma unroll
    for (int it = 0; it < 8; it++) {
        int slot = it * 256 + tid;
        int dk = slot >> 4, og = slot & 15;
        *(float4*)&sW2[dk * 64 + og * 4] = *(const float4*)&W2[dk * 64 + og * 4];
    }
    if (tid < 64) sW3[tid] = W3[tid];
    __syncthreads();
    const int stride = sAny ? 1 : 2;   // words per index element

    // GEMM thread mapping
    const int lx = lane & 15, ly = lane >> 4;
    const int o0  = lx * 4;            // 0..60
    const int el0 = w * 8 + ly * 4;    // local edge base, 0..60

    const float4 b2v  = __ldg((const float4*)&b2[o0]);
    const float  w30 = sW3[o0], w31 = sW3[o0 + 1], w32 = sW3[o0 + 2], w33 = sW3[o0 + 3];
    const float  bias3 = __ldg(&b3[0]);

    const float4* P4 = (const float4*)g_P;
    const int grid = gridDim.x;

    // ---- prefetch state: 8 (src,dst) float4 pairs per thread ----
    float4 va[8], vb[8];

    int t = blockIdx.x;
    if (t < nTiles) {
#pragma unroll
        for (int it = 0; it < 8; it++) {
            int e = t * 64 + it * 8 + w; if (e >= E) e = E - 1;
            int si = eidx_w[(long long)e * stride];
            int di = eidx_w[(long long)(E + e) * stride];
            si = min(max(si, 0), N - 1);
            di = min(max(di, 0), N - 1);
            va[it] = __ldg(&P4[(long long)si * 64 + lane]);
            vb[it] = __ldg(&P4[(long long)di * 64 + 32 + lane]);
        }
    }

    for (; t < nTiles; t += grid) {
        // ---- consume prefetched tile t: h1 = relu(src + dst) -> sH1 ----
#pragma unroll
        for (int it = 0; it < 8; it++) {
            int e = it * 8 + w;
            float4 h;
            h.x = fmaxf(va[it].x + vb[it].x, 0.f);
            h.y = fmaxf(va[it].y + vb[it].y, 0.f);
            h.z = fmaxf(va[it].z + vb[it].z, 0.f);
            h.w = fmaxf(va[it].w + vb[it].w, 0.f);
            *(float4*)&sH1[e * 128 + lane * 4] = h;
        }
        __syncthreads();

        // ---- issue prefetch for tile t+grid (hidden under GEMM) ----
        int tn = t + grid;
        if (tn < nTiles) {
#pragma unroll
            for (int it = 0; it < 8; it++) {
                int e = tn * 64 + it * 8 + w; if (e >= E) e = E - 1;
                int si = eidx_w[(long long)e * stride];
                int di = eidx_w[(long long)(E + e) * stride];
                si = min(max(si, 0), N - 1);
                di = min(max(di, 0), N - 1);
                va[it] = __ldg(&P4[(long long)si * 64 + lane]);
                vb[it] = __ldg(&P4[(long long)di * 64 + 32 + lane]);
            }
        }

        // ---- layer 2 GEMM: [64 edges x 128] @ [128 x 64] ----
        unsigned long long acc[4][2];
#pragma unroll
        for (int i = 0; i < 4; i++) { acc[i][0] = 0ull; acc[i][1] = 0ull; }

#pragma unroll
        for (int dk = 0; dk < 128; dk += 4) {
            float4 hv[4];
#pragma unroll
            for (int i = 0; i < 4; i++)
                hv[i] = *(const float4*)&sH1[(el0 + i) * 128 + dk];
#pragma unroll
            for (int kk = 0; kk < 4; kk++) {
                ulonglong2 wv = *(const ulonglong2*)&sW2[(dk + kk) * 64 + o0];
#pragma unroll
                for (int i = 0; i < 4; i++) {
                    float hx = (kk == 0) ? hv[i].x : (kk == 1) ? hv[i].y
                             : (kk == 2) ? hv[i].z : hv[i].w;
                    unsigned long long hh = pack2(hx, hx);
                    fma2(acc[i][0], hh, wv.x);
                    fma2(acc[i][1], hh, wv.y);
                }
            }
        }

        // ---- epilogue: +b2, relu, dot W3, 16-lane reduce, +b3, store ----
#pragma unroll
        for (int i = 0; i < 4; i++) {
            float v0, v1, v2, v3;
            unpack2(acc[i][0], v0, v1);
            unpack2(acc[i][1], v2, v3);
            float s = fmaxf(v0 + b2v.x, 0.f) * w30
                    + fmaxf(v1 + b2v.y, 0.f) * w31
                    + fmaxf(v2 + b2v.z, 0.f) * w32
                    + fmaxf(v3 + b2v.w, 0.f) * w33;
            s += __shfl_xor_sync(0xffffffffu, s, 8);
            s += __shfl_xor_sync(0xffffffffu, s, 4);
            s += __shfl_xor_sync(0xffffffffu, s, 2);
            s += __shfl_xor_sync(0xffffffffu, s, 1);
            if (lx == 0) {
                int e = t * 64 + el0 + i;
                if (e < E) out[e] = s + bias3;
            }
        }
        __syncthreads();   // sH1 reuse guard for next iteration's consume
    }
}

// ---------------------------------------------------------------------------
extern "C" void kernel_launch(void* const* d_in, const int* in_sizes, int n_in,
                              void* d_out, int out_size) {
    const float* emb    = (const float*)d_in[0];
    const int*   eidx_w = (const int*)d_in[1];     // raw 32-bit words
    const float* W1     = (const float*)d_in[2];
    const float* b1     = (const float*)d_in[3];
    const float* W2     = (const float*)d_in[4];
    const float* b2     = (const float*)d_in[5];
    const float* W3     = (const float*)d_in[6];
    const float* b3     = (const float*)d_in[7];

    int N = in_sizes[0] / 128;   // node count
    int E = in_sizes[1] / 2;     // edge count (elements, dtype-independent)
    int nTiles = (E + 63) / 64;

    static int smem_set = 0;
    if (!smem_set) {
        cudaFuncSetAttribute(edge_kernel,
                             cudaFuncAttributeMaxDynamicSharedMemorySize,
                             EDGE_SMEM_BYTES);
        smem_set = 1;
    }

    precompute_kernel<<<(N + 63) / 64, 256>>>(emb, W1, b1, N);
    edge_kernel<<<2 * NSM, 256, EDGE_SMEM_BYTES>>>(eidx_w, W2, b2, W3, b3,
                                                   (float*)d_out, E, N, nTiles);
}